// round 9
// baseline (speedup 1.0000x reference)
#include <cuda_runtime.h>
#include <cuda_fp16.h>
#include <cstdint>

#define BB 24
#define DM 128
#define HH 8
#define DK 16
#define LL 512
#define HB (HH*BB)   // 192

__device__ float g_head[BB*DM*LL];    // [b][h*16+v][l]

// ---- mma/ldmatrix helpers ----
__device__ __forceinline__ uint32_t smem_u32(const void* p) {
    uint32_t a;
    asm("{ .reg .u64 t; cvta.to.shared.u64 t, %1; cvt.u32.u64 %0, t; }" : "=r"(a) : "l"(p));
    return a;
}
__device__ __forceinline__ void ldsm4(uint32_t* r, uint32_t a) {
    asm volatile("ldmatrix.sync.aligned.m8n8.x4.shared.b16 {%0,%1,%2,%3}, [%4];"
        : "=r"(r[0]), "=r"(r[1]), "=r"(r[2]), "=r"(r[3]) : "r"(a));
}
__device__ __forceinline__ void ldsm4t(uint32_t* r, uint32_t a) {
    asm volatile("ldmatrix.sync.aligned.m8n8.x4.trans.shared.b16 {%0,%1,%2,%3}, [%4];"
        : "=r"(r[0]), "=r"(r[1]), "=r"(r[2]), "=r"(r[3]) : "r"(a));
}
__device__ __forceinline__ void mma_f16(float* d, const uint32_t* a, const uint32_t* b) {
    asm volatile("mma.sync.aligned.m16n8k16.row.col.f32.f16.f16.f32 "
        "{%0,%1,%2,%3}, {%4,%5,%6,%7}, {%8,%9}, {%0,%1,%2,%3};"
        : "+f"(d[0]), "+f"(d[1]), "+f"(d[2]), "+f"(d[3])
        : "r"(a[0]), "r"(a[1]), "r"(a[2]), "r"(a[3]), "r"(b[0]), "r"(b[1]));
}
__device__ __forceinline__ float ex2f(float x) {
    float r; asm("ex2.approx.f32 %0, %1;" : "=f"(r) : "f"(x)); return r;
}
__device__ __forceinline__ void packhl(float p0, float p1, uint32_t& h, uint32_t& l) {
    __half2 hh = __floats2half2_rn(p0, p1);
    float2 f = __half22float2(hh);
    __half2 ll = __floats2half2_rn(p0 - f.x, p1 - f.y);
    h = *(uint32_t*)&hh; l = *(uint32_t*)&ll;
}
__device__ __forceinline__ uint32_t packh(float p0, float p1) {
    __half2 hh = __floats2half2_rn(p0, p1);
    return *(uint32_t*)&hh;
}

// =====================================================================
// Fused QKV + attention. Grid 192 (hb), 512 threads.
// Phase 1: QKV projection via mma.sync fp16 hi/lo, fragments written
//          straight into attention-layout smem (no gmem round trip).
// Phase 2: flash-style attention (identical math to R8 k_attn).
// =====================================================================
#define F_WH 0          // W hi: 48*136*2 = 13056
#define F_WL 13056
#define F_XH 26112      // x chunk hi: 128*136*2 = 34816
#define F_XL 60928
#define F_QH 95744      // each QKV buf: 16*520*2 = 16640
#define F_QL 112384
#define F_KH 129024
#define F_KL 145664
#define F_VH 162304
#define F_VL 178944
#define F_SMEM 195584

__global__ void __launch_bounds__(512, 1) k_fused(const float* __restrict__ x,
                                                  const float* __restrict__ Wq,
                                                  const float* __restrict__ Wk,
                                                  const float* __restrict__ Wv)
{
    extern __shared__ char smc[];
    const uint32_t su = smem_u32(smc);
    const int t = threadIdx.x, w = t >> 5, ln = t & 31;
    const int hb = blockIdx.x, b = hb % BB, h = hb / BB;

    __half* sWh = (__half*)(smc + F_WH);
    __half* sWl = (__half*)(smc + F_WL);
    __half* sXh = (__half*)(smc + F_XH);
    __half* sXl = (__half*)(smc + F_XL);
    __half* sQh = (__half*)(smc + F_QH);
    __half* sQl = (__half*)(smc + F_QL);
    __half* sKh = (__half*)(smc + F_KH);
    __half* sKl = (__half*)(smc + F_KL);
    __half* sVh = (__half*)(smc + F_VH);
    __half* sVl = (__half*)(smc + F_VL);

    const int rsel = ln & 15;
    const uint32_t csel = (uint32_t)(ln >> 4) * 16;
    const int trow = (ln & 7) + ((ln >> 4) << 3);
    const uint32_t tcb = (uint32_t)((ln >> 3) & 1) * 16;

    // ---------------- Phase 1: QKV projection ----------------
    // stage W = [Wq;Wk;Wv] (48 x 128) hi/lo
    for (int i4 = t; i4 < 1536; i4 += 512) {
        int r = i4 >> 5, c4 = i4 & 31;
        const float* src = (r < 16) ? (Wq + (size_t)hb*2048 + r*128)
                         : (r < 32) ? (Wk + (size_t)hb*2048 + (r-16)*128)
                                    : (Wv + (size_t)hb*2048 + (r-32)*128);
        float4 v = *(const float4*)(src + c4*4);
        uint32_t h0,l0,h1,l1;
        packhl(v.x, v.y, h0, l0); packhl(v.z, v.w, h1, l1);
        uint2 uh; uh.x = h0; uh.y = h1;
        uint2 ul; ul.x = l0; ul.y = l1;
        *(uint2*)&sWh[r*136 + c4*4] = uh;
        *(uint2*)&sWl[r*136 + c4*4] = ul;
    }

    const float* xb = x + (size_t)b * 65536;
    const int ls = w & 7, grp = w >> 3;   // ls: l-slice of 16; grp 0: Q,K  1: V
    const int nmt = grp ? 1 : 2;

    // prefetch chunk 0 into registers
    float4 xr[8];
    #pragma unroll
    for (int j = 0; j < 8; ++j) {
        int i4 = t + j*512; int d = i4 >> 5, l4 = i4 & 31;
        xr[j] = *(const float4*)(xb + (size_t)d*512 + l4*4);
    }

    for (int lt = 0; lt < 4; ++lt) {
        __syncthreads();   // sX free (prev chunk's MMAs done); also covers W staging on iter 0
        #pragma unroll
        for (int j = 0; j < 8; ++j) {
            int i4 = t + j*512; int d = i4 >> 5, l4 = i4 & 31;
            uint32_t h0,l0,h1,l1;
            packhl(xr[j].x, xr[j].y, h0, l0); packhl(xr[j].z, xr[j].w, h1, l1);
            uint2 uh; uh.x = h0; uh.y = h1;
            uint2 ul; ul.x = l0; ul.y = l1;
            *(uint2*)&sXh[d*136 + l4*4] = uh;
            *(uint2*)&sXl[d*136 + l4*4] = ul;
        }
        __syncthreads();
        if (lt < 3) {      // prefetch next chunk; latency hidden behind MMAs below
            #pragma unroll
            for (int j = 0; j < 8; ++j) {
                int i4 = t + j*512; int d = i4 >> 5, l4 = i4 & 31;
                xr[j] = *(const float4*)(xb + (size_t)d*512 + (lt+1)*128 + l4*4);
            }
        }

        float acc[2][2][4];
        #pragma unroll
        for (int mt = 0; mt < 2; ++mt)
            #pragma unroll
            for (int nt = 0; nt < 2; ++nt)
                #pragma unroll
                for (int r = 0; r < 4; ++r) acc[mt][nt][r] = 0.f;

        #pragma unroll
        for (int kt = 0; kt < 8; ++kt) {
            uint32_t bh[2][2], bl[2][2], r4[4];
            uint32_t ad = su + F_XH + (uint32_t)((kt*16 + trow)*272) + (uint32_t)(ls*16)*2 + tcb;
            ldsm4t(r4, ad);
            bh[0][0]=r4[0]; bh[0][1]=r4[2]; bh[1][0]=r4[1]; bh[1][1]=r4[3];
            ldsm4t(r4, ad + (F_XL - F_XH));
            bl[0][0]=r4[0]; bl[0][1]=r4[2]; bl[1][0]=r4[1]; bl[1][1]=r4[3];
            #pragma unroll
            for (int mt = 0; mt < 2; ++mt) {
                if (mt >= nmt) break;
                int wrow = (grp ? 2 : mt) * 16 + rsel;
                uint32_t ah[4], al[4];
                uint32_t aad = su + F_WH + (uint32_t)(wrow*272) + csel + kt*32;
                ldsm4(ah, aad);
                ldsm4(al, aad + (F_WL - F_WH));
                #pragma unroll
                for (int nt = 0; nt < 2; ++nt) {
                    mma_f16(acc[mt][nt], ah, bh[nt]);
                    mma_f16(acc[mt][nt], ah, bl[nt]);
                    mma_f16(acc[mt][nt], al, bh[nt]);
                }
            }
        }

        // epilogue: fragments -> QKV smem (hi/lo), layout [k][l] pitch 520
        #pragma unroll
        for (int mt = 0; mt < 2; ++mt) {
            if (mt >= nmt) break;
            __half* dh = grp ? sVh : (mt ? sKh : sQh);
            __half* dl = grp ? sVl : (mt ? sKl : sQl);
            #pragma unroll
            for (int nt = 0; nt < 2; ++nt) {
                int rr = ln >> 2;
                int cc = lt*128 + ls*16 + nt*8 + (ln & 3)*2;
                uint32_t h0,l0,h1,l1;
                packhl(acc[mt][nt][0], acc[mt][nt][1], h0, l0);
                packhl(acc[mt][nt][2], acc[mt][nt][3], h1, l1);
                *(uint32_t*)&dh[rr*520 + cc]     = h0;
                *(uint32_t*)&dl[rr*520 + cc]     = l0;
                *(uint32_t*)&dh[(rr+8)*520 + cc] = h1;
                *(uint32_t*)&dl[(rr+8)*520 + cc] = l1;
            }
        }
    }
    __syncthreads();

    // ---------------- Phase 2: attention ----------------
    uint32_t kh[2][4], kl[2][4];
    #pragma unroll
    for (int mt = 0; mt < 2; ++mt) {
        uint32_t ad = su + F_KH + (uint32_t)(trow*1040) + (uint32_t)((w*32 + mt*16)*2) + tcb;
        ldsm4t(kh[mt], ad);
        ldsm4t(kl[mt], ad + (F_KL - F_KH));
    }

    float mx[2][2], dn[2][2], O[2][2][4];
    #pragma unroll
    for (int mt = 0; mt < 2; ++mt)
        #pragma unroll
        for (int j = 0; j < 2; ++j) {
            mx[mt][j] = -1e30f; dn[mt][j] = 0.f;
            #pragma unroll
            for (int r = 0; r < 4; ++r) O[mt][j][r] = 0.f;
        }

    const float C = 0.36067376022224085f;   // 0.25 * log2(e)

    for (int c = 0; c < 16; ++c) {
        uint32_t qbh[4][2], qbl[4][2];
        #pragma unroll
        for (int q = 0; q < 2; ++q) {
            uint32_t r4[4];
            uint32_t ad = su + F_QH + (uint32_t)(trow*1040) + (uint32_t)((c*32 + q*16)*2) + tcb;
            ldsm4t(r4, ad);
            qbh[2*q][0]=r4[0]; qbh[2*q][1]=r4[2]; qbh[2*q+1][0]=r4[1]; qbh[2*q+1][1]=r4[3];
            ldsm4t(r4, ad + (F_QL - F_QH));
            qbl[2*q][0]=r4[0]; qbl[2*q][1]=r4[2]; qbl[2*q+1][0]=r4[1]; qbl[2*q+1][1]=r4[3];
        }

        float s[2][4][4];
        #pragma unroll
        for (int mt = 0; mt < 2; ++mt)
            #pragma unroll
            for (int nt = 0; nt < 4; ++nt) {
                #pragma unroll
                for (int r = 0; r < 4; ++r) s[mt][nt][r] = 0.f;
                mma_f16(s[mt][nt], kh[mt], qbh[nt]);
                mma_f16(s[mt][nt], kh[mt], qbl[nt]);
                mma_f16(s[mt][nt], kl[mt], qbh[nt]);
            }

        #pragma unroll
        for (int mt = 0; mt < 2; ++mt) {
            float cA = -1e30f, cB = -1e30f;
            #pragma unroll
            for (int nt = 0; nt < 4; ++nt) {
                cA = fmaxf(cA, fmaxf(s[mt][nt][0], s[mt][nt][1]));
                cB = fmaxf(cB, fmaxf(s[mt][nt][2], s[mt][nt][3]));
            }
            cA = fmaxf(cA, __shfl_xor_sync(0xffffffffu, cA, 1));
            cA = fmaxf(cA, __shfl_xor_sync(0xffffffffu, cA, 2));
            cB = fmaxf(cB, __shfl_xor_sync(0xffffffffu, cB, 1));
            cB = fmaxf(cB, __shfl_xor_sync(0xffffffffu, cB, 2));
            float mA = fmaxf(mx[mt][0], cA), mB = fmaxf(mx[mt][1], cB);
            float sA = ex2f((mx[mt][0] - mA) * C), sB = ex2f((mx[mt][1] - mB) * C);
            mx[mt][0] = mA; mx[mt][1] = mB;
            dn[mt][0] *= sA; dn[mt][1] *= sB;
            #pragma unroll
            for (int vt = 0; vt < 2; ++vt) {
                O[mt][vt][0] *= sA; O[mt][vt][1] *= sA;
                O[mt][vt][2] *= sB; O[mt][vt][3] *= sB;
            }
            #pragma unroll
            for (int nt = 0; nt < 4; ++nt) {
                float p0 = ex2f((s[mt][nt][0] - mA) * C);
                float p1 = ex2f((s[mt][nt][1] - mA) * C);
                float p2 = ex2f((s[mt][nt][2] - mB) * C);
                float p3 = ex2f((s[mt][nt][3] - mB) * C);
                dn[mt][0] += p0 + p1; dn[mt][1] += p2 + p3;
                s[mt][nt][0] = p0; s[mt][nt][1] = p1;
                s[mt][nt][2] = p2; s[mt][nt][3] = p3;
            }
        }

        #pragma unroll
        for (int st = 0; st < 2; ++st) {
            uint32_t vbh[2][2], vbl[2][2], r4[4];
            uint32_t ad = su + F_VH + (uint32_t)(rsel * 1040 + (c*32 + st*16) * 2) + csel;
            ldsm4(r4, ad);
            vbh[0][0]=r4[0]; vbh[0][1]=r4[2]; vbh[1][0]=r4[1]; vbh[1][1]=r4[3];
            ldsm4(r4, ad + (F_VL - F_VH));
            vbl[0][0]=r4[0]; vbl[0][1]=r4[2]; vbl[1][0]=r4[1]; vbl[1][1]=r4[3];

            #pragma unroll
            for (int mt = 0; mt < 2; ++mt) {
                uint32_t ah[4];
                ah[0] = packh(s[mt][2*st][0],   s[mt][2*st][1]);
                ah[1] = packh(s[mt][2*st][2],   s[mt][2*st][3]);
                ah[2] = packh(s[mt][2*st+1][0], s[mt][2*st+1][1]);
                ah[3] = packh(s[mt][2*st+1][2], s[mt][2*st+1][3]);
                #pragma unroll
                for (int vt = 0; vt < 2; ++vt) {
                    mma_f16(O[mt][vt], ah, vbh[vt]);
                    mma_f16(O[mt][vt], ah, vbl[vt]);
                }
            }
        }
    }

    float inv[2][2];
    #pragma unroll
    for (int mt = 0; mt < 2; ++mt)
        #pragma unroll
        for (int j = 0; j < 2; ++j) {
            dn[mt][j] += __shfl_xor_sync(0xffffffffu, dn[mt][j], 1);
            dn[mt][j] += __shfl_xor_sync(0xffffffffu, dn[mt][j], 2);
            inv[mt][j] = 1.0f / dn[mt][j];
        }

    float* dst = g_head + ((size_t)b * DM + h * DK) * LL;
    #pragma unroll
    for (int mt = 0; mt < 2; ++mt)
        #pragma unroll
        for (int vt = 0; vt < 2; ++vt)
            #pragma unroll
            for (int r = 0; r < 4; ++r) {
                int m = w*32 + mt*16 + (ln >> 2) + ((r >> 1) & 1) * 8;
                int v = vt*8 + (ln & 3)*2 + (r & 1);
                dst[(size_t)v * LL + m] = O[mt][vt][r] * inv[mt][(r >> 1) & 1];
            }
}

// =====================================================================
// Kernel 3: out = Wo @ head. Grid (8 lt of 64 l, 24 b), 256 thr.
// =====================================================================
#define OW_H 0          // 128*136*2 = 34816
#define OW_L 34816
#define OX_H 69632      // 128*72*2 = 18432
#define OX_L 88064
#define O_SMEM 106496

__global__ __launch_bounds__(256) void k_out(const float* __restrict__ Wo,
                                             float* __restrict__ out)
{
    extern __shared__ char smc[];
    const uint32_t su = smem_u32(smc);
    __half* sWh = (__half*)(smc + OW_H);
    __half* sWl = (__half*)(smc + OW_L);
    __half* sXh = (__half*)(smc + OX_H);
    __half* sXl = (__half*)(smc + OX_L);
    const int t = threadIdx.x, w = t >> 5, ln = t & 31;
    const int lt = blockIdx.x, b = blockIdx.y;
    const int lg = w & 3, mh = w >> 2;
    const int rsel = ln & 15;
    const uint32_t csel = (uint32_t)(ln >> 4) * 16;
    const int trow = (ln & 7) + ((ln >> 4) << 3);
    const uint32_t tcb = (uint32_t)((ln >> 3) & 1) * 16;

    for (int i4 = t; i4 < 4096; i4 += 256) {
        int r = i4 >> 5, c4 = i4 & 31;
        float4 v = *(const float4*)(Wo + (size_t)b*16384 + (size_t)r*128 + c4*4);
        uint32_t h0,l0,h1,l1;
        packhl(v.x, v.y, h0, l0); packhl(v.z, v.w, h1, l1);
        uint2 uh; uh.x = h0; uh.y = h1;
        uint2 ul; ul.x = l0; ul.y = l1;
        *(uint2*)&sWh[r*136 + c4*4] = uh;
        *(uint2*)&sWl[r*136 + c4*4] = ul;
    }
    for (int i4 = t; i4 < 2048; i4 += 256) {
        int d = i4 >> 4, l4 = i4 & 15;
        float4 xv = *(const float4*)(g_head + (size_t)b*65536 + (size_t)d*512 + lt*64 + l4*4);
        uint32_t h0,l0,h1,l1;
        packhl(xv.x, xv.y, h0, l0); packhl(xv.z, xv.w, h1, l1);
        uint2 uh; uh.x = h0; uh.y = h1;
        uint2 ul; ul.x = l0; ul.y = l1;
        *(uint2*)&sXh[d*72 + l4*4] = uh;
        *(uint2*)&sXl[d*72 + l4*4] = ul;
    }
    __syncthreads();

    float acc[4][2][4];
    #pragma unroll
    for (int mt = 0; mt < 4; ++mt)
        #pragma unroll
        for (int nt = 0; nt < 2; ++nt)
            #pragma unroll
            for (int r = 0; r < 4; ++r) acc[mt][nt][r] = 0.f;

    #pragma unroll
    for (int kt = 0; kt < 8; ++kt) {
        uint32_t bh[2][2], bl[2][2], r4[4];
        uint32_t ad = su + OX_H + (uint32_t)((kt*16 + trow)*144) + (uint32_t)(lg*16)*2 + tcb;
        ldsm4t(r4, ad);
        bh[0][0]=r4[0]; bh[0][1]=r4[2]; bh[1][0]=r4[1]; bh[1][1]=r4[3];
        ldsm4t(r4, ad + (OX_L - OX_H));
        bl[0][0]=r4[0]; bl[0][1]=r4[2]; bl[1][0]=r4[1]; bl[1][1]=r4[3];
        #pragma unroll
        for (int mt = 0; mt < 4; ++mt) {
            uint32_t ah[4], al[4];
            uint32_t aad = su + OW_H + (uint32_t)(((mh*4 + mt)*16 + rsel)*272) + csel + kt*32;
            ldsm4(ah, aad);
            ldsm4(al, aad + (OW_L - OW_H));
            #pragma unroll
            for (int nt = 0; nt < 2; ++nt) {
                mma_f16(acc[mt][nt], ah, bh[nt]);
                mma_f16(acc[mt][nt], ah, bl[nt]);
                mma_f16(acc[mt][nt], al, bh[nt]);
            }
        }
    }

    #pragma unroll
    for (int mt = 0; mt < 4; ++mt)
        #pragma unroll
        for (int nt = 0; nt < 2; ++nt) {
            int rr = (mh*4 + mt)*16 + (ln >> 2);
            int cc = lt*64 + lg*16 + nt*8 + (ln & 3)*2;
            float2 v0; v0.x = acc[mt][nt][0]; v0.y = acc[mt][nt][1];
            float2 v1; v1.x = acc[mt][nt][2]; v1.y = acc[mt][nt][3];
            *(float2*)&out[(size_t)b*DM*LL + (size_t)rr*512 + cc]     = v0;
            *(float2*)&out[(size_t)b*DM*LL + (size_t)(rr+8)*512 + cc] = v1;
        }
}

// =====================================================================
extern "C" void kernel_launch(void* const* d_in, const int* in_sizes, int n_in,
                              void* d_out, int out_size)
{
    const float* x  = (const float*)d_in[0];
    const float* Wq = (const float*)d_in[1];
    const float* Wk = (const float*)d_in[2];
    const float* Wv = (const float*)d_in[3];
    const float* Wo = (const float*)d_in[4];
    float* out = (float*)d_out;

    cudaFuncSetAttribute(k_fused, cudaFuncAttributeMaxDynamicSharedMemorySize, F_SMEM);
    cudaFuncSetAttribute(k_out,   cudaFuncAttributeMaxDynamicSharedMemorySize, O_SMEM);

    k_fused<<<HB, 512, F_SMEM>>>(x, Wq, Wk, Wv);
    k_out<<<dim3(8, BB), 256, O_SMEM>>>(Wo, out);
}

// round 10
// speedup vs baseline: 1.0874x; 1.0874x over previous
#include <cuda_runtime.h>
#include <cuda_fp16.h>
#include <cstdint>

#define BB 24
#define DM 128
#define HH 8
#define DK 16
#define LL 512
#define HB (HH*BB)   // 192

__device__ float g_head[BB*DM*LL];    // [b][h*16+v][l]

// ---- mma/ldmatrix helpers ----
__device__ __forceinline__ uint32_t smem_u32(const void* p) {
    uint32_t a;
    asm("{ .reg .u64 t; cvta.to.shared.u64 t, %1; cvt.u32.u64 %0, t; }" : "=r"(a) : "l"(p));
    return a;
}
__device__ __forceinline__ void ldsm4(uint32_t* r, uint32_t a) {
    asm volatile("ldmatrix.sync.aligned.m8n8.x4.shared.b16 {%0,%1,%2,%3}, [%4];"
        : "=r"(r[0]), "=r"(r[1]), "=r"(r[2]), "=r"(r[3]) : "r"(a));
}
__device__ __forceinline__ void ldsm4t(uint32_t* r, uint32_t a) {
    asm volatile("ldmatrix.sync.aligned.m8n8.x4.trans.shared.b16 {%0,%1,%2,%3}, [%4];"
        : "=r"(r[0]), "=r"(r[1]), "=r"(r[2]), "=r"(r[3]) : "r"(a));
}
__device__ __forceinline__ void mma_f16(float* d, const uint32_t* a, const uint32_t* b) {
    asm volatile("mma.sync.aligned.m16n8k16.row.col.f32.f16.f16.f32 "
        "{%0,%1,%2,%3}, {%4,%5,%6,%7}, {%8,%9}, {%0,%1,%2,%3};"
        : "+f"(d[0]), "+f"(d[1]), "+f"(d[2]), "+f"(d[3])
        : "r"(a[0]), "r"(a[1]), "r"(a[2]), "r"(a[3]), "r"(b[0]), "r"(b[1]));
}
__device__ __forceinline__ float ex2f(float x) {
    float r; asm("ex2.approx.f32 %0, %1;" : "=f"(r) : "f"(x)); return r;
}
__device__ __forceinline__ void packhl(float p0, float p1, uint32_t& h, uint32_t& l) {
    __half2 hh = __floats2half2_rn(p0, p1);
    float2 f = __half22float2(hh);
    __half2 ll = __floats2half2_rn(p0 - f.x, p1 - f.y);
    h = *(uint32_t*)&hh; l = *(uint32_t*)&ll;
}
__device__ __forceinline__ uint32_t packh(float p0, float p1) {
    __half2 hh = __floats2half2_rn(p0, p1);
    return *(uint32_t*)&hh;
}

// =====================================================================
// Fused QKV + attention. Grid 192 (hb), 512 threads.
// =====================================================================
#define F_WH 0          // W hi: 48*136*2 = 13056
#define F_WL 13056
#define F_XH 26112      // x chunk hi: 128*136*2 = 34816
#define F_XL 60928
#define F_QH 95744      // Q/K hi,lo: 16*520*2 = 16640 each; V hi only
#define F_QL 112384
#define F_KH 129024
#define F_KL 145664
#define F_VH 162304
#define F_SMEM 178944

__device__ __forceinline__ void load_qfrag(uint32_t base, int c, int trow, uint32_t tcb,
                                           uint32_t dst[4][2]) {
    #pragma unroll
    for (int q = 0; q < 2; ++q) {
        uint32_t r4[4];
        uint32_t ad = base + (uint32_t)(trow*1040) + (uint32_t)((c*32 + q*16)*2) + tcb;
        ldsm4t(r4, ad);
        dst[2*q][0]=r4[0]; dst[2*q][1]=r4[2]; dst[2*q+1][0]=r4[1]; dst[2*q+1][1]=r4[3];
    }
}

__device__ __forceinline__ void attn_iter(int c, uint32_t su, int trow, uint32_t tcb,
                                          int rsel, uint32_t csel,
                                          uint32_t kh[2][4], uint32_t kl[2][4],
                                          uint32_t qcur[4][2], uint32_t qnxt[4][2],
                                          float mx[2][2], float dn[2][2], float O[2][2][4],
                                          bool pre) {
    const float C = 0.36067376022224085f;   // 0.25 * log2(e)

    // V fragments (hi only) for this chunk — loaded early, consumed after softmax
    uint32_t vb[2][2][2];
    #pragma unroll
    for (int st = 0; st < 2; ++st) {
        uint32_t r4[4];
        uint32_t ad = su + F_VH + (uint32_t)(rsel * 1040 + (c*32 + st*16) * 2) + csel;
        ldsm4(r4, ad);
        vb[st][0][0]=r4[0]; vb[st][0][1]=r4[2]; vb[st][1][0]=r4[1]; vb[st][1][1]=r4[3];
    }
    // Q_lo fragments
    uint32_t ql[4][2];
    load_qfrag(su + F_QL, c, trow, tcb, ql);

    // scores: Q_lo-independent terms first (cover ql/vb ldsm latency)
    float s[2][4][4];
    #pragma unroll
    for (int mt = 0; mt < 2; ++mt)
        #pragma unroll
        for (int nt = 0; nt < 4; ++nt) {
            #pragma unroll
            for (int r = 0; r < 4; ++r) s[mt][nt][r] = 0.f;
            mma_f16(s[mt][nt], kh[mt], qcur[nt]);
            mma_f16(s[mt][nt], kl[mt], qcur[nt]);
        }
    if (pre) load_qfrag(su + F_QH, c + 1, trow, tcb, qnxt);
    #pragma unroll
    for (int mt = 0; mt < 2; ++mt)
        #pragma unroll
        for (int nt = 0; nt < 4; ++nt)
            mma_f16(s[mt][nt], kh[mt], ql[nt]);

    // online softmax
    #pragma unroll
    for (int mt = 0; mt < 2; ++mt) {
        float cA = -1e30f, cB = -1e30f;
        #pragma unroll
        for (int nt = 0; nt < 4; ++nt) {
            cA = fmaxf(cA, fmaxf(s[mt][nt][0], s[mt][nt][1]));
            cB = fmaxf(cB, fmaxf(s[mt][nt][2], s[mt][nt][3]));
        }
        cA = fmaxf(cA, __shfl_xor_sync(0xffffffffu, cA, 1));
        cA = fmaxf(cA, __shfl_xor_sync(0xffffffffu, cA, 2));
        cB = fmaxf(cB, __shfl_xor_sync(0xffffffffu, cB, 1));
        cB = fmaxf(cB, __shfl_xor_sync(0xffffffffu, cB, 2));
        float mA = fmaxf(mx[mt][0], cA), mB = fmaxf(mx[mt][1], cB);
        float sA = ex2f((mx[mt][0] - mA) * C), sB = ex2f((mx[mt][1] - mB) * C);
        mx[mt][0] = mA; mx[mt][1] = mB;
        dn[mt][0] *= sA; dn[mt][1] *= sB;
        #pragma unroll
        for (int vt = 0; vt < 2; ++vt) {
            O[mt][vt][0] *= sA; O[mt][vt][1] *= sA;
            O[mt][vt][2] *= sB; O[mt][vt][3] *= sB;
        }
        #pragma unroll
        for (int nt = 0; nt < 4; ++nt) {
            float p0 = ex2f((s[mt][nt][0] - mA) * C);
            float p1 = ex2f((s[mt][nt][1] - mA) * C);
            float p2 = ex2f((s[mt][nt][2] - mB) * C);
            float p3 = ex2f((s[mt][nt][3] - mB) * C);
            dn[mt][0] += p0 + p1; dn[mt][1] += p2 + p3;
            s[mt][nt][0] = p0; s[mt][nt][1] = p1;
            s[mt][nt][2] = p2; s[mt][nt][3] = p3;
        }
    }

    // O += P_hi * V_hi
    #pragma unroll
    for (int st = 0; st < 2; ++st)
        #pragma unroll
        for (int mt = 0; mt < 2; ++mt) {
            uint32_t ah[4];
            ah[0] = packh(s[mt][2*st][0],   s[mt][2*st][1]);
            ah[1] = packh(s[mt][2*st][2],   s[mt][2*st][3]);
            ah[2] = packh(s[mt][2*st+1][0], s[mt][2*st+1][1]);
            ah[3] = packh(s[mt][2*st+1][2], s[mt][2*st+1][3]);
            #pragma unroll
            for (int vt = 0; vt < 2; ++vt)
                mma_f16(O[mt][vt], ah, vb[st][vt]);
        }
}

__global__ void __launch_bounds__(512, 1) k_fused(const float* __restrict__ x,
                                                  const float* __restrict__ Wq,
                                                  const float* __restrict__ Wk,
                                                  const float* __restrict__ Wv)
{
    extern __shared__ char smc[];
    const uint32_t su = smem_u32(smc);
    const int t = threadIdx.x, w = t >> 5, ln = t & 31;
    const int hb = blockIdx.x, b = hb % BB, h = hb / BB;

    __half* sWh = (__half*)(smc + F_WH);
    __half* sWl = (__half*)(smc + F_WL);
    __half* sXh = (__half*)(smc + F_XH);
    __half* sXl = (__half*)(smc + F_XL);
    __half* sQh = (__half*)(smc + F_QH);
    __half* sQl = (__half*)(smc + F_QL);
    __half* sKh = (__half*)(smc + F_KH);
    __half* sKl = (__half*)(smc + F_KL);
    __half* sVh = (__half*)(smc + F_VH);

    const int rsel = ln & 15;
    const uint32_t csel = (uint32_t)(ln >> 4) * 16;
    const int trow = (ln & 7) + ((ln >> 4) << 3);
    const uint32_t tcb = (uint32_t)((ln >> 3) & 1) * 16;

    // ---------------- Phase 1: QKV projection ----------------
    for (int i4 = t; i4 < 1536; i4 += 512) {
        int r = i4 >> 5, c4 = i4 & 31;
        const float* src = (r < 16) ? (Wq + (size_t)hb*2048 + r*128)
                         : (r < 32) ? (Wk + (size_t)hb*2048 + (r-16)*128)
                                    : (Wv + (size_t)hb*2048 + (r-32)*128);
        float4 v = *(const float4*)(src + c4*4);
        uint32_t h0,l0,h1,l1;
        packhl(v.x, v.y, h0, l0); packhl(v.z, v.w, h1, l1);
        uint2 uh; uh.x = h0; uh.y = h1;
        uint2 ul; ul.x = l0; ul.y = l1;
        *(uint2*)&sWh[r*136 + c4*4] = uh;
        *(uint2*)&sWl[r*136 + c4*4] = ul;
    }

    const float* xb = x + (size_t)b * 65536;
    const int ls = w & 7, grp = w >> 3;
    const int nmt = grp ? 1 : 2;

    float4 xr[8];
    #pragma unroll
    for (int j = 0; j < 8; ++j) {
        int i4 = t + j*512; int d = i4 >> 5, l4 = i4 & 31;
        xr[j] = *(const float4*)(xb + (size_t)d*512 + l4*4);
    }

    for (int lt = 0; lt < 4; ++lt) {
        __syncthreads();
        #pragma unroll
        for (int j = 0; j < 8; ++j) {
            int i4 = t + j*512; int d = i4 >> 5, l4 = i4 & 31;
            uint32_t h0,l0,h1,l1;
            packhl(xr[j].x, xr[j].y, h0, l0); packhl(xr[j].z, xr[j].w, h1, l1);
            uint2 uh; uh.x = h0; uh.y = h1;
            uint2 ul; ul.x = l0; ul.y = l1;
            *(uint2*)&sXh[d*136 + l4*4] = uh;
            *(uint2*)&sXl[d*136 + l4*4] = ul;
        }
        __syncthreads();
        if (lt < 3) {
            #pragma unroll
            for (int j = 0; j < 8; ++j) {
                int i4 = t + j*512; int d = i4 >> 5, l4 = i4 & 31;
                xr[j] = *(const float4*)(xb + (size_t)d*512 + (lt+1)*128 + l4*4);
            }
        }

        float acc[2][2][4];
        #pragma unroll
        for (int mt = 0; mt < 2; ++mt)
            #pragma unroll
            for (int nt = 0; nt < 2; ++nt)
                #pragma unroll
                for (int r = 0; r < 4; ++r) acc[mt][nt][r] = 0.f;

        #pragma unroll
        for (int kt = 0; kt < 8; ++kt) {
            uint32_t bh[2][2], bl[2][2], r4[4];
            uint32_t ad = su + F_XH + (uint32_t)((kt*16 + trow)*272) + (uint32_t)(ls*16)*2 + tcb;
            ldsm4t(r4, ad);
            bh[0][0]=r4[0]; bh[0][1]=r4[2]; bh[1][0]=r4[1]; bh[1][1]=r4[3];
            ldsm4t(r4, ad + (F_XL - F_XH));
            bl[0][0]=r4[0]; bl[0][1]=r4[2]; bl[1][0]=r4[1]; bl[1][1]=r4[3];
            #pragma unroll
            for (int mt = 0; mt < 2; ++mt) {
                if (mt >= nmt) break;
                int wrow = (grp ? 2 : mt) * 16 + rsel;
                uint32_t ah[4], al[4];
                uint32_t aad = su + F_WH + (uint32_t)(wrow*272) + csel + kt*32;
                ldsm4(ah, aad);
                ldsm4(al, aad + (F_WL - F_WH));
                #pragma unroll
                for (int nt = 0; nt < 2; ++nt) {
                    mma_f16(acc[mt][nt], ah, bh[nt]);
                    mma_f16(acc[mt][nt], ah, bl[nt]);
                    mma_f16(acc[mt][nt], al, bh[nt]);
                }
            }
        }

        #pragma unroll
        for (int mt = 0; mt < 2; ++mt) {
            if (mt >= nmt) break;
            #pragma unroll
            for (int nt = 0; nt < 2; ++nt) {
                int rr = ln >> 2;
                int cc = lt*128 + ls*16 + nt*8 + (ln & 3)*2;
                if (grp) {   // V: hi only
                    *(uint32_t*)&sVh[rr*520 + cc]     = packh(acc[mt][nt][0], acc[mt][nt][1]);
                    *(uint32_t*)&sVh[(rr+8)*520 + cc] = packh(acc[mt][nt][2], acc[mt][nt][3]);
                } else {
                    __half* dh = mt ? sKh : sQh;
                    __half* dl = mt ? sKl : sQl;
                    uint32_t h0,l0,h1,l1;
                    packhl(acc[mt][nt][0], acc[mt][nt][1], h0, l0);
                    packhl(acc[mt][nt][2], acc[mt][nt][3], h1, l1);
                    *(uint32_t*)&dh[rr*520 + cc]     = h0;
                    *(uint32_t*)&dl[rr*520 + cc]     = l0;
                    *(uint32_t*)&dh[(rr+8)*520 + cc] = h1;
                    *(uint32_t*)&dl[(rr+8)*520 + cc] = l1;
                }
            }
        }
    }
    __syncthreads();

    // ---------------- Phase 2: attention ----------------
    uint32_t kh[2][4], kl[2][4];
    #pragma unroll
    for (int mt = 0; mt < 2; ++mt) {
        uint32_t ad = su + F_KH + (uint32_t)(trow*1040) + (uint32_t)((w*32 + mt*16)*2) + tcb;
        ldsm4t(kh[mt], ad);
        ldsm4t(kl[mt], ad + (F_KL - F_KH));
    }

    float mx[2][2], dn[2][2], O[2][2][4];
    #pragma unroll
    for (int mt = 0; mt < 2; ++mt)
        #pragma unroll
        for (int j = 0; j < 2; ++j) {
            mx[mt][j] = -1e30f; dn[mt][j] = 0.f;
            #pragma unroll
            for (int r = 0; r < 4; ++r) O[mt][j][r] = 0.f;
        }

    uint32_t qhA[4][2], qhB[4][2];
    load_qfrag(su + F_QH, 0, trow, tcb, qhA);

    for (int c2 = 0; c2 < 16; c2 += 2) {
        attn_iter(c2,     su, trow, tcb, rsel, csel, kh, kl, qhA, qhB, mx, dn, O, true);
        attn_iter(c2 + 1, su, trow, tcb, rsel, csel, kh, kl, qhB, qhA, mx, dn, O, c2 < 14);
    }

    float inv[2][2];
    #pragma unroll
    for (int mt = 0; mt < 2; ++mt)
        #pragma unroll
        for (int j = 0; j < 2; ++j) {
            dn[mt][j] += __shfl_xor_sync(0xffffffffu, dn[mt][j], 1);
            dn[mt][j] += __shfl_xor_sync(0xffffffffu, dn[mt][j], 2);
            inv[mt][j] = 1.0f / dn[mt][j];
        }

    float* dst = g_head + ((size_t)b * DM + h * DK) * LL;
    #pragma unroll
    for (int mt = 0; mt < 2; ++mt)
        #pragma unroll
        for (int vt = 0; vt < 2; ++vt)
            #pragma unroll
            for (int r = 0; r < 4; ++r) {
                int m = w*32 + mt*16 + (ln >> 2) + ((r >> 1) & 1) * 8;
                int v = vt*8 + (ln & 3)*2 + (r & 1);
                dst[(size_t)v * LL + m] = O[mt][vt][r] * inv[mt][(r >> 1) & 1];
            }
}

// =====================================================================
// Kernel 3: out = Wo @ head. Grid (8 lt x 2 mh x 24 b) = 384 CTAs,
// 256 thr = 4 l-groups x 2 m-groups. 72KB smem -> 3 CTAs/SM.
// =====================================================================
#define OW_H 0          // 64*136*2 = 17408
#define OW_L 17408
#define OX_H 34816      // 128*72*2 = 18432
#define OX_L 53248
#define O_SMEM 71680

__global__ __launch_bounds__(256) void k_out(const float* __restrict__ Wo,
                                             float* __restrict__ out)
{
    extern __shared__ char smc[];
    const uint32_t su = smem_u32(smc);
    __half* sWh = (__half*)(smc + OW_H);
    __half* sWl = (__half*)(smc + OW_L);
    __half* sXh = (__half*)(smc + OX_H);
    __half* sXl = (__half*)(smc + OX_L);
    const int t = threadIdx.x, w = t >> 5, ln = t & 31;
    const int lt = blockIdx.x, mh = blockIdx.y, b = blockIdx.z;
    const int lg = w & 3, mg = w >> 2;
    const int rsel = ln & 15;
    const uint32_t csel = (uint32_t)(ln >> 4) * 16;
    const int trow = (ln & 7) + ((ln >> 4) << 3);
    const uint32_t tcb = (uint32_t)((ln >> 3) & 1) * 16;

    // stage Wo half (64 rows)
    for (int i4 = t; i4 < 2048; i4 += 256) {
        int r = i4 >> 5, c4 = i4 & 31;
        float4 v = *(const float4*)(Wo + (size_t)b*16384 + (size_t)(mh*64 + r)*128 + c4*4);
        uint32_t h0,l0,h1,l1;
        packhl(v.x, v.y, h0, l0); packhl(v.z, v.w, h1, l1);
        uint2 uh; uh.x = h0; uh.y = h1;
        uint2 ul; ul.x = l0; ul.y = l1;
        *(uint2*)&sWh[r*136 + c4*4] = uh;
        *(uint2*)&sWl[r*136 + c4*4] = ul;
    }
    // stage head chunk (64 l)
    for (int i4 = t; i4 < 2048; i4 += 256) {
        int d = i4 >> 4, l4 = i4 & 15;
        float4 xv = *(const float4*)(g_head + (size_t)b*65536 + (size_t)d*512 + lt*64 + l4*4);
        uint32_t h0,l0,h1,l1;
        packhl(xv.x, xv.y, h0, l0); packhl(xv.z, xv.w, h1, l1);
        uint2 uh; uh.x = h0; uh.y = h1;
        uint2 ul; ul.x = l0; ul.y = l1;
        *(uint2*)&sXh[d*72 + l4*4] = uh;
        *(uint2*)&sXl[d*72 + l4*4] = ul;
    }
    __syncthreads();

    float acc[2][2][4];
    #pragma unroll
    for (int mt = 0; mt < 2; ++mt)
        #pragma unroll
        for (int nt = 0; nt < 2; ++nt)
            #pragma unroll
            for (int r = 0; r < 4; ++r) acc[mt][nt][r] = 0.f;

    #pragma unroll
    for (int kt = 0; kt < 8; ++kt) {
        uint32_t bh[2][2], bl[2][2], r4[4];
        uint32_t ad = su + OX_H + (uint32_t)((kt*16 + trow)*144) + (uint32_t)(lg*16)*2 + tcb;
        ldsm4t(r4, ad);
        bh[0][0]=r4[0]; bh[0][1]=r4[2]; bh[1][0]=r4[1]; bh[1][1]=r4[3];
        ldsm4t(r4, ad + (OX_L - OX_H));
        bl[0][0]=r4[0]; bl[0][1]=r4[2]; bl[1][0]=r4[1]; bl[1][1]=r4[3];
        #pragma unroll
        for (int mt = 0; mt < 2; ++mt) {
            uint32_t ah[4], al[4];
            uint32_t aad = su + OW_H + (uint32_t)(((mg*2 + mt)*16 + rsel)*272) + csel + kt*32;
            ldsm4(ah, aad);
            ldsm4(al, aad + (OW_L - OW_H));
            #pragma unroll
            for (int nt = 0; nt < 2; ++nt) {
                mma_f16(acc[mt][nt], ah, bh[nt]);
                mma_f16(acc[mt][nt], ah, bl[nt]);
                mma_f16(acc[mt][nt], al, bh[nt]);
            }
        }
    }

    #pragma unroll
    for (int mt = 0; mt < 2; ++mt)
        #pragma unroll
        for (int nt = 0; nt < 2; ++nt) {
            int rr = mh*64 + (mg*2 + mt)*16 + (ln >> 2);
            int cc = lt*64 + lg*16 + nt*8 + (ln & 3)*2;
            float2 v0; v0.x = acc[mt][nt][0]; v0.y = acc[mt][nt][1];
            float2 v1; v1.x = acc[mt][nt][2]; v1.y = acc[mt][nt][3];
            *(float2*)&out[(size_t)b*65536 + (size_t)rr*512 + cc]     = v0;
            *(float2*)&out[(size_t)b*65536 + (size_t)(rr+8)*512 + cc] = v1;
        }
}

// =====================================================================
extern "C" void kernel_launch(void* const* d_in, const int* in_sizes, int n_in,
                              void* d_out, int out_size)
{
    const float* x  = (const float*)d_in[0];
    const float* Wq = (const float*)d_in[1];
    const float* Wk = (const float*)d_in[2];
    const float* Wv = (const float*)d_in[3];
    const float* Wo = (const float*)d_in[4];
    float* out = (float*)d_out;

    cudaFuncSetAttribute(k_fused, cudaFuncAttributeMaxDynamicSharedMemorySize, F_SMEM);
    cudaFuncSetAttribute(k_out,   cudaFuncAttributeMaxDynamicSharedMemorySize, O_SMEM);

    k_fused<<<HB, 512, F_SMEM>>>(x, Wq, Wk, Wv);
    k_out<<<dim3(8, 2, BB), 256, O_SMEM>>>(Wo, out);
}

// round 11
// speedup vs baseline: 1.2190x; 1.1210x over previous
#include <cuda_runtime.h>
#include <cuda_fp16.h>
#include <cstdint>

#define BB 24
#define DM 128
#define HH 8
#define DK 16
#define LL 512
#define HB (HH*BB)   // 192

// fp16 hi/lo intermediates (allocation-free: __device__ globals)
__device__ __half gQh[HB*DK*LL], gQl[HB*DK*LL];
__device__ __half gKh[HB*DK*LL], gKl[HB*DK*LL];
__device__ __half gVh[HB*DK*LL];
__device__ __half gHh[BB*DM*LL], gHl[BB*DM*LL];

// ---- mma/ldmatrix helpers ----
__device__ __forceinline__ uint32_t smem_u32(const void* p) {
    uint32_t a;
    asm("{ .reg .u64 t; cvta.to.shared.u64 t, %1; cvt.u32.u64 %0, t; }" : "=r"(a) : "l"(p));
    return a;
}
__device__ __forceinline__ void ldsm4(uint32_t* r, uint32_t a) {
    asm volatile("ldmatrix.sync.aligned.m8n8.x4.shared.b16 {%0,%1,%2,%3}, [%4];"
        : "=r"(r[0]), "=r"(r[1]), "=r"(r[2]), "=r"(r[3]) : "r"(a));
}
__device__ __forceinline__ void ldsm4t(uint32_t* r, uint32_t a) {
    asm volatile("ldmatrix.sync.aligned.m8n8.x4.trans.shared.b16 {%0,%1,%2,%3}, [%4];"
        : "=r"(r[0]), "=r"(r[1]), "=r"(r[2]), "=r"(r[3]) : "r"(a));
}
__device__ __forceinline__ void mma_f16(float* d, const uint32_t* a, const uint32_t* b) {
    asm volatile("mma.sync.aligned.m16n8k16.row.col.f32.f16.f16.f32 "
        "{%0,%1,%2,%3}, {%4,%5,%6,%7}, {%8,%9}, {%0,%1,%2,%3};"
        : "+f"(d[0]), "+f"(d[1]), "+f"(d[2]), "+f"(d[3])
        : "r"(a[0]), "r"(a[1]), "r"(a[2]), "r"(a[3]), "r"(b[0]), "r"(b[1]));
}
__device__ __forceinline__ float ex2f(float x) {
    float r; asm("ex2.approx.f32 %0, %1;" : "=f"(r) : "f"(x)); return r;
}
__device__ __forceinline__ void packhl(float p0, float p1, uint32_t& h, uint32_t& l) {
    __half2 hh = __floats2half2_rn(p0, p1);
    float2 f = __half22float2(hh);
    __half2 ll = __floats2half2_rn(p0 - f.x, p1 - f.y);
    h = *(uint32_t*)&hh; l = *(uint32_t*)&ll;
}
__device__ __forceinline__ uint32_t packh(float p0, float p1) {
    __half2 hh = __floats2half2_rn(p0, p1);
    return *(uint32_t*)&hh;
}
__device__ __forceinline__ void split1(float v, __half& h, __half& l) {
    h = __float2half_rn(v);
    l = __float2half_rn(v - __half2float(h));
}

// =====================================================================
// Kernel 1: QKV projection. Grid 384 = (hb, lt-half), 256 thr.
// Term-split accumulators (3 chains of 8). Outputs fp16 hi/lo gmem.
// =====================================================================
#define QW_H 0          // 48*136*2 = 13056
#define QW_L 13056
#define QX_H 26112      // 128*136*2 = 34816
#define QX_L 60928
#define Q_SMEM 95744

__global__ __launch_bounds__(256) void k_qkv(const float* __restrict__ x,
                                             const float* __restrict__ Wq,
                                             const float* __restrict__ Wk,
                                             const float* __restrict__ Wv)
{
    extern __shared__ char smc[];
    const uint32_t su = smem_u32(smc);
    __half* sWh = (__half*)(smc + QW_H);
    __half* sWl = (__half*)(smc + QW_L);
    __half* sXh = (__half*)(smc + QX_H);
    __half* sXl = (__half*)(smc + QX_L);
    const int t = threadIdx.x, w = t >> 5, ln = t & 31;
    const int hb = blockIdx.x >> 1, half = blockIdx.x & 1;
    const int b = hb % BB;
    const int rsel = ln & 15;
    const uint32_t csel = (uint32_t)(ln >> 4) * 16;
    const int trow = (ln & 7) + ((ln >> 4) << 3);
    const uint32_t tcb = (uint32_t)((ln >> 3) & 1) * 16;

    for (int i4 = t; i4 < 1536; i4 += 256) {
        int r = i4 >> 5, c4 = i4 & 31;
        const float* src = (r < 16) ? (Wq + (size_t)hb*2048 + r*128)
                         : (r < 32) ? (Wk + (size_t)hb*2048 + (r-16)*128)
                                    : (Wv + (size_t)hb*2048 + (r-32)*128);
        float4 v = *(const float4*)(src + c4*4);
        uint32_t h0,l0,h1,l1;
        packhl(v.x, v.y, h0, l0); packhl(v.z, v.w, h1, l1);
        uint2 uh; uh.x = h0; uh.y = h1;
        uint2 ul; ul.x = l0; ul.y = l1;
        *(uint2*)&sWh[r*136 + c4*4] = uh;
        *(uint2*)&sWl[r*136 + c4*4] = ul;
    }

    for (int lt = half*2; lt < half*2 + 2; ++lt) {
        __syncthreads();
        for (int i4 = t; i4 < 4096; i4 += 256) {
            int d = i4 >> 5, l4 = i4 & 31;
            float4 xv = *(const float4*)(x + (size_t)b*65536 + (size_t)d*512 + lt*128 + l4*4);
            uint32_t h0,l0,h1,l1;
            packhl(xv.x, xv.y, h0, l0); packhl(xv.z, xv.w, h1, l1);
            uint2 uh; uh.x = h0; uh.y = h1;
            uint2 ul; ul.x = l0; ul.y = l1;
            *(uint2*)&sXh[d*136 + l4*4] = uh;
            *(uint2*)&sXl[d*136 + l4*4] = ul;
        }
        __syncthreads();

        float aHH[3][2][4], aHL[3][2][4], aLH[3][2][4];
        #pragma unroll
        for (int mt = 0; mt < 3; ++mt)
            #pragma unroll
            for (int nt = 0; nt < 2; ++nt)
                #pragma unroll
                for (int r = 0; r < 4; ++r) { aHH[mt][nt][r]=0.f; aHL[mt][nt][r]=0.f; aLH[mt][nt][r]=0.f; }

        #pragma unroll
        for (int kt = 0; kt < 8; ++kt) {
            uint32_t bh[2][2], bl[2][2], r4[4];
            uint32_t ad = su + QX_H + (uint32_t)((kt*16 + trow)*272) + (uint32_t)(w*16)*2 + tcb;
            ldsm4t(r4, ad);
            bh[0][0]=r4[0]; bh[0][1]=r4[2]; bh[1][0]=r4[1]; bh[1][1]=r4[3];
            ldsm4t(r4, ad + (QX_L - QX_H));
            bl[0][0]=r4[0]; bl[0][1]=r4[2]; bl[1][0]=r4[1]; bl[1][1]=r4[3];
            #pragma unroll
            for (int mt = 0; mt < 3; ++mt) {
                uint32_t ah[4], al[4];
                uint32_t aad = su + QW_H + (uint32_t)((mt*16 + rsel)*272) + csel + kt*32;
                ldsm4(ah, aad);
                ldsm4(al, aad + (QW_L - QW_H));
                #pragma unroll
                for (int nt = 0; nt < 2; ++nt) {
                    mma_f16(aHH[mt][nt], ah, bh[nt]);
                    mma_f16(aHL[mt][nt], ah, bl[nt]);
                    mma_f16(aLH[mt][nt], al, bh[nt]);
                }
            }
        }

        #pragma unroll
        for (int mt = 0; mt < 3; ++mt) {
            #pragma unroll
            for (int nt = 0; nt < 2; ++nt) {
                int rr = ln >> 2;
                int cc = lt*128 + w*16 + nt*8 + (ln & 3)*2;
                float v0 = aHH[mt][nt][0] + aHL[mt][nt][0] + aLH[mt][nt][0];
                float v1 = aHH[mt][nt][1] + aHL[mt][nt][1] + aLH[mt][nt][1];
                float v2 = aHH[mt][nt][2] + aHL[mt][nt][2] + aLH[mt][nt][2];
                float v3 = aHH[mt][nt][3] + aHL[mt][nt][3] + aLH[mt][nt][3];
                size_t o0 = (size_t)hb*8192 + (size_t)rr*512 + cc;
                size_t o1 = (size_t)hb*8192 + (size_t)(rr+8)*512 + cc;
                if (mt == 2) {
                    *(uint32_t*)&gVh[o0] = packh(v0, v1);
                    *(uint32_t*)&gVh[o1] = packh(v2, v3);
                } else {
                    __half* dh = mt ? gKh : gQh;
                    __half* dl = mt ? gKl : gQl;
                    uint32_t h0,l0,h1,l1;
                    packhl(v0, v1, h0, l0); packhl(v2, v3, h1, l1);
                    *(uint32_t*)&dh[o0] = h0; *(uint32_t*)&dl[o0] = l0;
                    *(uint32_t*)&dh[o1] = h1; *(uint32_t*)&dl[o1] = l1;
                }
            }
        }
    }
}

// =====================================================================
// Kernel 2: attention. Grid 768 = (hb, m-slice of 128), 256 thr,
// 8 warps x 16 m-rows. Low-register variant -> 3 CTAs/SM target.
// =====================================================================
#define A_QH 0          // 16*520*2 = 16640
#define A_QL 16640
#define A_VH 33280
#define A_KH 49920      // 16*136*2 = 4352
#define A_KL 54272
#define A_SMEM 58624

__global__ void __launch_bounds__(256, 3) k_attn()
{
    extern __shared__ char smc[];
    const uint32_t su = smem_u32(smc);
    const int t = threadIdx.x, w = t >> 5, ln = t & 31;
    const int hb = blockIdx.x >> 2, ms = blockIdx.x & 3;
    const int b = hb % BB, h = hb / BB;
    const int m0 = ms * 128;

    // stage Q hi/lo + V hi (full 512 l), pitch 520 halves
    {
        const __half* s0 = gQh + (size_t)hb*8192;
        const __half* s1 = gQl + (size_t)hb*8192;
        const __half* s2 = gVh + (size_t)hb*8192;
        for (int j = t; j < 1024; j += 256) {
            int k = j >> 6, c = j & 63;
            uint32_t dofs = (uint32_t)(k*1040 + c*16);
            *(uint4*)(smc + A_QH + dofs) = *(const uint4*)(s0 + k*512 + c*8);
            *(uint4*)(smc + A_QL + dofs) = *(const uint4*)(s1 + k*512 + c*8);
            *(uint4*)(smc + A_VH + dofs) = *(const uint4*)(s2 + k*512 + c*8);
        }
        // K slice (128 m cols), pitch 136 halves
        for (int j = t; j < 256; j += 256) {
            int k = j >> 4, c = j & 15;
            uint32_t dofs = (uint32_t)(k*272 + c*16);
            *(uint4*)(smc + A_KH + dofs) = *(const uint4*)(gKh + (size_t)hb*8192 + k*512 + m0 + c*8);
            *(uint4*)(smc + A_KL + dofs) = *(const uint4*)(gKl + (size_t)hb*8192 + k*512 + m0 + c*8);
        }
    }
    __syncthreads();

    const int rsel = ln & 15;
    const uint32_t csel = (uint32_t)(ln >> 4) * 16;
    const int trow = (ln & 7) + ((ln >> 4) << 3);
    const uint32_t tcb = (uint32_t)((ln >> 3) & 1) * 16;

    // resident K fragments (this warp's 16 m-rows)
    uint32_t kh[4], kl[4];
    {
        uint32_t ad = su + A_KH + (uint32_t)(trow*272) + (uint32_t)(w*16)*2 + tcb;
        ldsm4t(kh, ad);
        ldsm4t(kl, ad + (A_KL - A_KH));
    }

    float mx[2] = {-1e30f, -1e30f}, dn[2] = {0.f, 0.f}, O[2][4];
    #pragma unroll
    for (int vt = 0; vt < 2; ++vt)
        #pragma unroll
        for (int r = 0; r < 4; ++r) O[vt][r] = 0.f;

    const float C = 0.36067376022224085f;   // 0.25 * log2(e)

    for (int c = 0; c < 16; ++c) {
        // V fragments (hi only)
        uint32_t vb[2][2][2];
        #pragma unroll
        for (int st = 0; st < 2; ++st) {
            uint32_t r4[4];
            uint32_t ad = su + A_VH + (uint32_t)(rsel * 1040 + (c*32 + st*16) * 2) + csel;
            ldsm4(r4, ad);
            vb[st][0][0]=r4[0]; vb[st][0][1]=r4[2]; vb[st][1][0]=r4[1]; vb[st][1][1]=r4[3];
        }
        // Q fragments hi + lo
        uint32_t qh[4][2], ql[4][2];
        #pragma unroll
        for (int q = 0; q < 2; ++q) {
            uint32_t r4[4];
            uint32_t ad = su + A_QH + (uint32_t)(trow*1040) + (uint32_t)((c*32 + q*16)*2) + tcb;
            ldsm4t(r4, ad);
            qh[2*q][0]=r4[0]; qh[2*q][1]=r4[2]; qh[2*q+1][0]=r4[1]; qh[2*q+1][1]=r4[3];
            ldsm4t(r4, ad + (A_QL - A_QH));
            ql[2*q][0]=r4[0]; ql[2*q][1]=r4[2]; ql[2*q+1][0]=r4[1]; ql[2*q+1][1]=r4[3];
        }

        // scores (3-term)
        float s[4][4];
        #pragma unroll
        for (int nt = 0; nt < 4; ++nt) {
            #pragma unroll
            for (int r = 0; r < 4; ++r) s[nt][r] = 0.f;
            mma_f16(s[nt], kh, qh[nt]);
            mma_f16(s[nt], kl, qh[nt]);
            mma_f16(s[nt], kh, ql[nt]);
        }

        // online softmax
        float cA = -1e30f, cB = -1e30f;
        #pragma unroll
        for (int nt = 0; nt < 4; ++nt) {
            cA = fmaxf(cA, fmaxf(s[nt][0], s[nt][1]));
            cB = fmaxf(cB, fmaxf(s[nt][2], s[nt][3]));
        }
        cA = fmaxf(cA, __shfl_xor_sync(0xffffffffu, cA, 1));
        cA = fmaxf(cA, __shfl_xor_sync(0xffffffffu, cA, 2));
        cB = fmaxf(cB, __shfl_xor_sync(0xffffffffu, cB, 1));
        cB = fmaxf(cB, __shfl_xor_sync(0xffffffffu, cB, 2));
        float mA = fmaxf(mx[0], cA), mB = fmaxf(mx[1], cB);
        float sA = ex2f((mx[0] - mA) * C), sB = ex2f((mx[1] - mB) * C);
        mx[0] = mA; mx[1] = mB;
        dn[0] *= sA; dn[1] *= sB;
        #pragma unroll
        for (int vt = 0; vt < 2; ++vt) {
            O[vt][0] *= sA; O[vt][1] *= sA;
            O[vt][2] *= sB; O[vt][3] *= sB;
        }
        #pragma unroll
        for (int nt = 0; nt < 4; ++nt) {
            float p0 = ex2f((s[nt][0] - mA) * C);
            float p1 = ex2f((s[nt][1] - mA) * C);
            float p2 = ex2f((s[nt][2] - mB) * C);
            float p3 = ex2f((s[nt][3] - mB) * C);
            dn[0] += p0 + p1; dn[1] += p2 + p3;
            s[nt][0] = p0; s[nt][1] = p1; s[nt][2] = p2; s[nt][3] = p3;
        }

        // O += P_hi * V_hi
        #pragma unroll
        for (int st = 0; st < 2; ++st) {
            uint32_t ah[4];
            ah[0] = packh(s[2*st][0],   s[2*st][1]);
            ah[1] = packh(s[2*st][2],   s[2*st][3]);
            ah[2] = packh(s[2*st+1][0], s[2*st+1][1]);
            ah[3] = packh(s[2*st+1][2], s[2*st+1][3]);
            #pragma unroll
            for (int vt = 0; vt < 2; ++vt)
                mma_f16(O[vt], ah, vb[st][vt]);
        }
    }

    float inv[2];
    #pragma unroll
    for (int j = 0; j < 2; ++j) {
        dn[j] += __shfl_xor_sync(0xffffffffu, dn[j], 1);
        dn[j] += __shfl_xor_sync(0xffffffffu, dn[j], 2);
        inv[j] = 1.0f / dn[j];
    }

    __half* dh = gHh + ((size_t)b * DM + h * DK) * LL;
    __half* dl = gHl + ((size_t)b * DM + h * DK) * LL;
    #pragma unroll
    for (int vt = 0; vt < 2; ++vt)
        #pragma unroll
        for (int r = 0; r < 4; ++r) {
            int m = m0 + w*16 + (ln >> 2) + ((r >> 1) & 1) * 8;
            int v = vt*8 + (ln & 3)*2 + (r & 1);
            float val = O[vt][r] * inv[(r >> 1) & 1];
            __half hi, lo; split1(val, hi, lo);
            dh[(size_t)v * LL + m] = hi;
            dl[(size_t)v * LL + m] = lo;
        }
}

// =====================================================================
// Kernel 3: out = Wo @ head. Grid (8 lt x 2 mh x 24 b), 256 thr.
// head staged by direct fp16 copies; term-split accumulators.
// =====================================================================
#define OW_H 0          // 64*136*2 = 17408
#define OW_L 17408
#define OX_H 34816      // 128*72*2 = 18432
#define OX_L 53248
#define O_SMEM 71680

__global__ __launch_bounds__(256) void k_out(const float* __restrict__ Wo,
                                             float* __restrict__ out)
{
    extern __shared__ char smc[];
    const uint32_t su = smem_u32(smc);
    __half* sWh = (__half*)(smc + OW_H);
    __half* sWl = (__half*)(smc + OW_L);
    const int t = threadIdx.x, w = t >> 5, ln = t & 31;
    const int lt = blockIdx.x, mh = blockIdx.y, b = blockIdx.z;
    const int lg = w & 3, mg = w >> 2;
    const int rsel = ln & 15;
    const uint32_t csel = (uint32_t)(ln >> 4) * 16;
    const int trow = (ln & 7) + ((ln >> 4) << 3);
    const uint32_t tcb = (uint32_t)((ln >> 3) & 1) * 16;

    for (int i4 = t; i4 < 2048; i4 += 256) {
        int r = i4 >> 5, c4 = i4 & 31;
        float4 v = *(const float4*)(Wo + (size_t)b*16384 + (size_t)(mh*64 + r)*128 + c4*4);
        uint32_t h0,l0,h1,l1;
        packhl(v.x, v.y, h0, l0); packhl(v.z, v.w, h1, l1);
        uint2 uh; uh.x = h0; uh.y = h1;
        uint2 ul; ul.x = l0; ul.y = l1;
        *(uint2*)&sWh[r*136 + c4*4] = uh;
        *(uint2*)&sWl[r*136 + c4*4] = ul;
    }
    for (int i4 = t; i4 < 1024; i4 += 256) {
        int d = i4 >> 3, j = i4 & 7;
        uint32_t dofs = (uint32_t)(d*144 + j*16);
        *(uint4*)(smc + OX_H + dofs) = *(const uint4*)(gHh + (size_t)b*65536 + (size_t)d*512 + lt*64 + j*8);
        *(uint4*)(smc + OX_L + dofs) = *(const uint4*)(gHl + (size_t)b*65536 + (size_t)d*512 + lt*64 + j*8);
    }
    __syncthreads();

    float aHH[2][2][4], aHL[2][2][4], aLH[2][2][4];
    #pragma unroll
    for (int mt = 0; mt < 2; ++mt)
        #pragma unroll
        for (int nt = 0; nt < 2; ++nt)
            #pragma unroll
            for (int r = 0; r < 4; ++r) { aHH[mt][nt][r]=0.f; aHL[mt][nt][r]=0.f; aLH[mt][nt][r]=0.f; }

    #pragma unroll
    for (int kt = 0; kt < 8; ++kt) {
        uint32_t bh[2][2], bl[2][2], r4[4];
        uint32_t ad = su + OX_H + (uint32_t)((kt*16 + trow)*144) + (uint32_t)(lg*16)*2 + tcb;
        ldsm4t(r4, ad);
        bh[0][0]=r4[0]; bh[0][1]=r4[2]; bh[1][0]=r4[1]; bh[1][1]=r4[3];
        ldsm4t(r4, ad + (OX_L - OX_H));
        bl[0][0]=r4[0]; bl[0][1]=r4[2]; bl[1][0]=r4[1]; bl[1][1]=r4[3];
        #pragma unroll
        for (int mt = 0; mt < 2; ++mt) {
            uint32_t ah[4], al[4];
            uint32_t aad = su + OW_H + (uint32_t)(((mg*2 + mt)*16 + rsel)*272) + csel + kt*32;
            ldsm4(ah, aad);
            ldsm4(al, aad + (OW_L - OW_H));
            #pragma unroll
            for (int nt = 0; nt < 2; ++nt) {
                mma_f16(aHH[mt][nt], ah, bh[nt]);
                mma_f16(aHL[mt][nt], ah, bl[nt]);
                mma_f16(aLH[mt][nt], al, bh[nt]);
            }
        }
    }

    #pragma unroll
    for (int mt = 0; mt < 2; ++mt)
        #pragma unroll
        for (int nt = 0; nt < 2; ++nt) {
            int rr = mh*64 + (mg*2 + mt)*16 + (ln >> 2);
            int cc = lt*64 + lg*16 + nt*8 + (ln & 3)*2;
            float2 v0, v1;
            v0.x = aHH[mt][nt][0] + aHL[mt][nt][0] + aLH[mt][nt][0];
            v0.y = aHH[mt][nt][1] + aHL[mt][nt][1] + aLH[mt][nt][1];
            v1.x = aHH[mt][nt][2] + aHL[mt][nt][2] + aLH[mt][nt][2];
            v1.y = aHH[mt][nt][3] + aHL[mt][nt][3] + aLH[mt][nt][3];
            *(float2*)&out[(size_t)b*65536 + (size_t)rr*512 + cc]     = v0;
            *(float2*)&out[(size_t)b*65536 + (size_t)(rr+8)*512 + cc] = v1;
        }
}

// =====================================================================
extern "C" void kernel_launch(void* const* d_in, const int* in_sizes, int n_in,
                              void* d_out, int out_size)
{
    const float* x  = (const float*)d_in[0];
    const float* Wq = (const float*)d_in[1];
    const float* Wk = (const float*)d_in[2];
    const float* Wv = (const float*)d_in[3];
    const float* Wo = (const float*)d_in[4];
    float* out = (float*)d_out;

    cudaFuncSetAttribute(k_qkv,  cudaFuncAttributeMaxDynamicSharedMemorySize, Q_SMEM);
    cudaFuncSetAttribute(k_attn, cudaFuncAttributeMaxDynamicSharedMemorySize, A_SMEM);
    cudaFuncSetAttribute(k_out,  cudaFuncAttributeMaxDynamicSharedMemorySize, O_SMEM);

    k_qkv<<<HB * 2, 256, Q_SMEM>>>(x, Wq, Wk, Wv);
    k_attn<<<HB * 4, 256, A_SMEM>>>();
    k_out<<<dim3(8, 2, BB), 256, O_SMEM>>>(Wo, out);
}